// round 12
// baseline (speedup 1.0000x reference)
#include <cuda_runtime.h>
#include <cuda_bf16.h>
#include <stdint.h>
#include <math.h>

#define HID   768
#define INTER 1536
#define DK    128
#define NCOL  3200
#define XCOL  3328            // NCOL padded to multiple of 256
#define BATCH 4
#define SEQ   2048
#define MTOT  8192

#define KE1 (3*HID)
#define KES (3*DK)
#define KEA (3*SEQ)
#define KEO (3*INTER)

__device__ int   g_dummy;
__device__ float g_x [(size_t)MTOT * XCOL];
__device__ float g_A [(size_t)BATCH * SEQ * SEQ];
__device__ float g_scale[BATCH];
__device__ __nv_bfloat16 g_Hext [(size_t)MTOT * KE1];
__device__ __nv_bfloat16 g_Wiext[(size_t)KE1 * XCOL];
__device__ __nv_bfloat16 g_qwext[(size_t)MTOT * KES];
__device__ __nv_bfloat16 g_qkT  [(size_t)BATCH * KES * SEQ];
__device__ __nv_bfloat16 g_Pext [(size_t)BATCH * SEQ * KEA];
__device__ __nv_bfloat16 g_vext [(size_t)BATCH * KEA * INTER];
__device__ __nv_bfloat16 g_pvext[(size_t)MTOT * KEO];
__device__ __nv_bfloat16 g_Woext[(size_t)KEO * HID];

__device__ __forceinline__ void bsplit(float v, __nv_bfloat16& h, __nv_bfloat16& l) {
    h = __float2bfloat16(v);
    l = __float2bfloat16(v - __bfloat162float(h));
}
__device__ __forceinline__ uint32_t smem_u32(const void* p) {
    uint32_t a;
    asm("{ .reg .u64 t; cvta.to.shared.u64 t, %1; cvt.u32.u64 %0, t; }" : "=r"(a) : "l"(p));
    return a;
}
#define LDMX4(r0,r1,r2,r3,addr) \
    asm volatile("ldmatrix.sync.aligned.m8n8.x4.shared.b16 {%0,%1,%2,%3}, [%4];" \
        : "=r"(r0),"=r"(r1),"=r"(r2),"=r"(r3) : "r"(addr))
#define LDMT4(r0,r1,r2,r3,addr) \
    asm volatile("ldmatrix.sync.aligned.m8n8.x4.trans.shared.b16 {%0,%1,%2,%3}, [%4];" \
        : "=r"(r0),"=r"(r1),"=r"(r2),"=r"(r3) : "r"(addr))
#define MMA16816(d, a, b0, b1) \
    asm volatile("mma.sync.aligned.m16n8k16.row.col.f32.bf16.bf16.f32 " \
        "{%0,%1,%2,%3},{%4,%5,%6,%7},{%8,%9},{%0,%1,%2,%3};" \
        : "+f"((d)[0]),"+f"((d)[1]),"+f"((d)[2]),"+f"((d)[3]) \
        : "r"((a)[0]),"r"((a)[1]),"r"((a)[2]),"r"((a)[3]),"r"(b0),"r"(b1))

// profiling pad so that launch #6 is the first GEMM
__global__ void prof_pad() { g_dummy = 0; }

__global__ void compute_scale_k(const int* __restrict__ mask)
{
    int b = blockIdx.x, t = threadIdx.x;
    int s = 0;
    for (int i = t; i < SEQ; i += 256) s += mask[(long)b*SEQ + i];
#pragma unroll
    for (int o = 16; o > 0; o >>= 1) s += __shfl_xor_sync(0xffffffffu, s, o);
    __shared__ int red[8];
    if ((t & 31) == 0) red[t >> 5] = s;
    __syncthreads();
    if (t == 0) {
        int tot = 0;
#pragma unroll
        for (int i = 0; i < 8; i++) tot += red[i];
        g_scale[b] = logf((float)tot) / (6.2383246250395075f * 11.313708498984761f);
    }
}

__global__ void conv_H(const float* __restrict__ Hs)
{
    long idx = (long)blockIdx.x * 256 + threadIdx.x;
    long r = idx / HID; int c = (int)(idx % HID);
    __nv_bfloat16 h, l; bsplit(Hs[idx], h, l);
    __nv_bfloat16* p = g_Hext + r * KE1 + c;
    p[0] = h; p[HID] = h; p[2*HID] = l;
}

__global__ void conv_Wi(const float* __restrict__ Wi)
{
    long idx = (long)blockIdx.x * 256 + threadIdx.x;
    long r = idx / NCOL; int c = (int)(idx % NCOL);
    __nv_bfloat16 h, l; bsplit(Wi[idx], h, l);
    g_Wiext[ r          * (long)XCOL + c] = h;
    g_Wiext[(r +   HID) * (long)XCOL + c] = l;
    g_Wiext[(r + 2*HID) * (long)XCOL + c] = h;
}

// zero the pad columns of Wiext so GEMM1 reads defined data there
__global__ void pad_Wi()
{
    long idx = (long)blockIdx.x * 256 + threadIdx.x;   // KE1 * (XCOL-NCOL)
    long r = idx / (XCOL - NCOL); int c = (int)(idx % (XCOL - NCOL));
    g_Wiext[r * (long)XCOL + NCOL + c] = __float2bfloat16(0.f);
}

__global__ void conv_Wo(const float* __restrict__ Wo)
{
    long idx = (long)blockIdx.x * 256 + threadIdx.x;
    long r = idx / HID; int c = (int)(idx % HID);
    __nv_bfloat16 h, l; bsplit(Wo[idx], h, l);
    g_Woext[ r            * (long)HID + c] = h;
    g_Woext[(r +   INTER) * (long)HID + c] = l;
    g_Woext[(r + 2*INTER) * (long)HID + c] = h;
}

__global__ void conv_qk(const float* __restrict__ qg, const float* __restrict__ kg)
{
    long idx = (long)blockIdx.x * 256 + threadIdx.x;
    long gr = idx >> 7; int d = (int)(idx & (DK - 1));
    float xv = g_x[gr * XCOL + 2*INTER + d];
    __nv_bfloat16 h, l;
    bsplit(xv * qg[d] * kg[d], h, l);
    __nv_bfloat16* p = g_qwext + gr * KES + d;
    p[0] = h; p[DK] = h; p[2*DK] = l;
    bsplit(xv, h, l);
    long b = gr >> 11, n = gr & (SEQ - 1);
    __nv_bfloat16* q = g_qkT + b * (long)KES * SEQ + n;
    q[(long)d * SEQ]          = h;
    q[(long)(DK + d) * SEQ]   = l;
    q[(long)(2*DK + d) * SEQ] = h;
}

__global__ void conv_v(int dummy)
{
    long idx = (long)blockIdx.x * 256 + threadIdx.x;
    long gr = idx / INTER; int j = (int)(idx % INTER);
    float xv = g_x[gr * XCOL + INTER + j];
    __nv_bfloat16 h, l; bsplit(xv, h, l);
    long b = gr >> 11, n = gr & (SEQ - 1);
    __nv_bfloat16* p = g_vext + b * (long)KEA * INTER + j;
    p[ n          * (long)INTER] = h;
    p[(n +   SEQ) * (long)INTER] = l;
    p[(n + 2*SEQ) * (long)INTER] = h;
}

__global__ __launch_bounds__(256) void softmax_rows(int dummy)
{
    long gr = blockIdx.x;
    const float* p = g_A + gr * SEQ;
    long b = gr >> 11, m = gr & (SEQ - 1);
    __nv_bfloat16* pe = g_Pext + b * (long)SEQ * KEA + m * (long)KEA;

    int t = threadIdx.x;
    float v[8];
    float mx = -3.4e38f;
#pragma unroll
    for (int i = 0; i < 8; i++) { v[i] = p[t + (i << 8)]; mx = fmaxf(mx, v[i]); }
    __shared__ float smax[8], ssum[8];
#pragma unroll
    for (int o = 16; o > 0; o >>= 1) mx = fmaxf(mx, __shfl_xor_sync(0xffffffffu, mx, o));
    if ((t & 31) == 0) smax[t >> 5] = mx;
    __syncthreads();
    if (t < 32) {
        float m2 = (t < 8) ? smax[t] : -3.4e38f;
#pragma unroll
        for (int o = 4; o > 0; o >>= 1) m2 = fmaxf(m2, __shfl_xor_sync(0xffffffffu, m2, o));
        if (t == 0) smax[0] = m2;
    }
    __syncthreads();
    mx = smax[0];
    float s = 0.f;
#pragma unroll
    for (int i = 0; i < 8; i++) { v[i] = expf(v[i] - mx); s += v[i]; }
#pragma unroll
    for (int o = 16; o > 0; o >>= 1) s += __shfl_xor_sync(0xffffffffu, s, o);
    if ((t & 31) == 0) ssum[t >> 5] = s;
    __syncthreads();
    if (t < 32) {
        float m2 = (t < 8) ? ssum[t] : 0.f;
#pragma unroll
        for (int o = 4; o > 0; o >>= 1) m2 += __shfl_xor_sync(0xffffffffu, m2, o);
        if (t == 0) ssum[0] = m2;
    }
    __syncthreads();
    float inv = 1.0f / ssum[0];
#pragma unroll
    for (int i = 0; i < 8; i++) {
        int n = t + (i << 8);
        __nv_bfloat16 h, l; bsplit(v[i] * inv, h, l);
        pe[n] = h; pe[SEQ + n] = h; pe[2*SEQ + n] = l;
    }
}

// ---------------------------------------------------------------------------
// bf16 tensor-core GEMM: 128x256 CTA tile, 512 threads, warp grid 4x4,
// warp tile 32x64, BK=32, register-prefetch single-stage smem.
// ---------------------------------------------------------------------------
template<int MODE>
__global__ __launch_bounds__(512, 1) void bmma_gemm(
    const __nv_bfloat16* __restrict__ A, int lda, long sA,
    const __nv_bfloat16* __restrict__ B, int ldb, long sB,
    float* __restrict__ Cf, int ldc, long sC,
    __nv_bfloat16* __restrict__ Cb, long sCb,
    const float* __restrict__ U, long sU,
    const int* __restrict__ maskb,
    int K)
{
    const int bz = blockIdx.z;
    A += (long)bz * sA;
    B += (long)bz * sB;
    const int* mk = (MODE == 2) ? (maskb + (long)bz * SEQ) : nullptr;

    __shared__ __align__(16) __nv_bfloat16 As[128][40];
    __shared__ __align__(16) __nv_bfloat16 Bs[32][264];

    const int tid  = threadIdx.x;
    const int lane = tid & 31;
    const int wid  = tid >> 5;
    const int warp_m = wid >> 2;      // 0..3
    const int warp_n = wid & 3;       // 0..3
    const int brow = blockIdx.y * 128;
    const int bcol = blockIdx.x * 256;

    // A: 128x32 tile, 512 threads x 1 int4
    const int aRow = tid >> 2,  aCol = (tid & 3) * 8;
    // B: 32x256 tile, 512 threads x 2 int4 (16 elems each)
    const int bRow = tid >> 4,  bCol = (tid & 15) * 16;

    const __nv_bfloat16* Ag = A + (long)(brow + aRow) * lda + aCol;
    const __nv_bfloat16* Bg = B + (long)bRow * ldb + bcol + bCol;

    const uint32_t asBase = smem_u32(&As[0][0]);
    const uint32_t bsBase = smem_u32(&Bs[0][0]);
    const int aLmRow = warp_m * 32 + ((lane >> 3) & 1) * 8 + (lane & 7);
    const int aLmCol = (lane >> 4) * 8;
    const int bLmRow = ((lane >> 3) & 1) * 8 + (lane & 7);
    const int bLmCol = warp_n * 64 + (lane >> 4) * 8;

    float acc[2][8][4] = {};

    const int nK = K / 32;
    int4 ra  = *(const int4*)Ag;
    int4 rb0 = *(const int4*)Bg;
    int4 rb1 = *(const int4*)(Bg + 8);

    for (int kc = 0; kc < nK; kc++) {
        *(int4*)&As[aRow][aCol]     = ra;
        *(int4*)&Bs[bRow][bCol]     = rb0;
        *(int4*)&Bs[bRow][bCol + 8] = rb1;
        __syncthreads();

        if (kc + 1 < nK) {
            long ko = (long)(kc + 1) * 32;
            ra  = *(const int4*)(Ag + ko);
            rb0 = *(const int4*)(Bg + ko * ldb);
            rb1 = *(const int4*)(Bg + ko * ldb + 8);
        }

#pragma unroll
        for (int kk = 0; kk < 2; kk++) {
            uint32_t a[2][4];
#pragma unroll
            for (int mf = 0; mf < 2; mf++) {
                uint32_t addr = asBase + (uint32_t)(((aLmRow + mf*16) * 40 + aLmCol + kk*16) * 2);
                LDMX4(a[mf][0], a[mf][1], a[mf][2], a[mf][3], addr);
            }
            uint32_t b[4][4];
#pragma unroll
            for (int p = 0; p < 4; p++) {
                uint32_t addr = bsBase + (uint32_t)(((bLmRow + kk*16) * 264 + bLmCol + p*16) * 2);
                LDMT4(b[p][0], b[p][1], b[p][2], b[p][3], addr);
            }
#pragma unroll
            for (int mf = 0; mf < 2; mf++)
#pragma unroll
                for (int nf = 0; nf < 8; nf++)
                    MMA16816(acc[mf][nf], a[mf], b[nf >> 1][(nf & 1) * 2], b[nf >> 1][(nf & 1) * 2 + 1]);
        }
        __syncthreads();
    }

    const int lr = lane >> 2, lc = (lane & 3) * 2;
    float scl = (MODE == 2) ? g_scale[bz] : 0.f;

#pragma unroll
    for (int mf = 0; mf < 2; mf++) {
#pragma unroll
        for (int i = 0; i < 2; i++) {
            int row = brow + warp_m * 32 + mf * 16 + i * 8 + lr;
#pragma unroll
            for (int nf = 0; nf < 8; nf++) {
                int col = bcol + warp_n * 64 + nf * 8 + lc;
                float v0 = acc[mf][nf][i * 2 + 0];
                float v1 = acc[mf][nf][i * 2 + 1];
                if (MODE == 0) {
                    float* c = Cf + (long)bz * sC + (long)row * ldc + col;
                    c[0] = v0; c[1] = v1;
                } else if (MODE == 1) {
                    v0 = v0 / (1.0f + expf(-v0));
                    v1 = v1 / (1.0f + expf(-v1));
                    float* c = Cf + (long)bz * sC + (long)row * ldc + col;
                    c[0] = v0; c[1] = v1;
                } else if (MODE == 2) {
                    v0 *= scl; v1 *= scl;
                    if (mk[col]     == 0) v0 = -1e30f;
                    if (mk[col + 1] == 0) v1 = -1e30f;
                    float* c = Cf + (long)bz * sC + (long)row * ldc + col;
                    c[0] = v0; c[1] = v1;
                } else {
                    const float* u = U + (long)bz * sU + (long)row * XCOL + col;
                    v0 *= u[0]; v1 *= u[1];
                    __nv_bfloat16 h0, l0, h1, l1;
                    bsplit(v0, h0, l0); bsplit(v1, h1, l1);
                    __nv_bfloat16* c = Cb + (long)bz * sCb + (long)row * KEO + col;
                    *(__nv_bfloat162*)(c)           = __halves2bfloat162(h0, h1);
                    *(__nv_bfloat162*)(c + INTER)   = __halves2bfloat162(h0, h1);
                    *(__nv_bfloat162*)(c + 2*INTER) = __halves2bfloat162(l0, l1);
                }
            }
        }
    }
}

extern "C" void kernel_launch(void* const* d_in, const int* in_sizes, int n_in,
                              void* d_out, int out_size)
{
    (void)in_sizes; (void)n_in; (void)out_size;
    const float* hidden = (const float*)d_in[0];
    const float* Wi     = (const float*)d_in[1];
    const float* Wo     = (const float*)d_in[2];
    const float* qg     = (const float*)d_in[3];
    const float* kg     = (const float*)d_in[4];
    const int*   mask   = (const int*)  d_in[5];
    float* out = (float*)d_out;

    float *px, *pA;
    __nv_bfloat16 *pH, *pWi, *pqw, *pqkT, *pP, *pv, *ppv, *pWo;
    cudaGetSymbolAddress((void**)&px,  g_x);
    cudaGetSymbolAddress((void**)&pA,  g_A);
    cudaGetSymbolAddress((void**)&pH,  g_Hext);
    cudaGetSymbolAddress((void**)&pWi, g_Wiext);
    cudaGetSymbolAddress((void**)&pqw, g_qwext);
    cudaGetSymbolAddress((void**)&pqkT,g_qkT);
    cudaGetSymbolAddress((void**)&pP,  g_Pext);
    cudaGetSymbolAddress((void**)&pv,  g_vext);
    cudaGetSymbolAddress((void**)&ppv, g_pvext);
    cudaGetSymbolAddress((void**)&pWo, g_Woext);

    // launch order arranged so launch #6 (ncu -s 5 -c 1) is GEMM1
    prof_pad<<<1, 32>>>();                                     // 1
    compute_scale_k<<<BATCH, 256>>>(mask);                     // 2
    conv_H <<<(MTOT*HID)/256, 256>>>(hidden);                  // 3
    conv_Wi<<<(HID*NCOL)/256, 256>>>(Wi);                      // 4
    pad_Wi <<<(KE1*(XCOL-NCOL))/256, 256>>>();                 // 5

    bmma_gemm<1><<<dim3(XCOL/256, MTOT/128, 1), 512>>>(        // 6  <- profiled
        pH, KE1, 0, pWi, XCOL, 0, px, XCOL, 0,
        nullptr, 0, nullptr, 0, nullptr, KE1);

    conv_Wo<<<(INTER*HID)/256, 256>>>(Wo);                     // 7
    conv_qk<<<(MTOT*DK)/256, 256>>>(qg, kg);                   // 8
    conv_v <<<(MTOT*INTER)/256, 256>>>(0);                     // 9

    bmma_gemm<2><<<dim3(SEQ/256, SEQ/128, BATCH), 512>>>(      // 10
        pqw, KES, (long)SEQ*KES, pqkT, SEQ, (long)KES*SEQ,
        pA, SEQ, (long)SEQ*SEQ,
        nullptr, 0, nullptr, 0, mask, KES);

    softmax_rows<<<MTOT, 256>>>(0);                            // 11

    bmma_gemm<3><<<dim3(INTER/256, SEQ/128, BATCH), 512>>>(    // 12
        pP, KEA, (long)SEQ*KEA, pv, INTER, (long)KEA*INTER,
        nullptr, 0, 0,
        ppv, (long)SEQ*KEO, px, (long)SEQ*XCOL, nullptr, KEA);

    bmma_gemm<0><<<dim3(HID/256, MTOT/128, 1), 512>>>(         // 13
        ppv, KEO, 0, pWo, HID, 0, out, HID, 0,
        nullptr, 0, nullptr, 0, nullptr, KEO);
}

// round 13
// speedup vs baseline: 1.3653x; 1.3653x over previous
#include <cuda_runtime.h>
#include <cuda_bf16.h>
#include <stdint.h>
#include <math.h>

#define HID   768
#define INTER 1536
#define DK    128
#define NCOL  3200
#define BATCH 4
#define SEQ   2048
#define MTOT  8192

// 2-slab [h|l] extended-K sizes
#define KE1b (2*HID)     // 1536
#define KESb (2*DK)      // 256
#define KEAb (2*SEQ)     // 4096
#define KEOb (2*INTER)   // 3072

__device__ float g_x [(size_t)MTOT * NCOL];
__device__ float g_A [(size_t)BATCH * SEQ * SEQ];
__device__ float g_scale[BATCH];
__device__ __nv_bfloat16 g_Hext [(size_t)MTOT * KE1b];
__device__ __nv_bfloat16 g_Wiext[(size_t)KE1b * NCOL];
__device__ __nv_bfloat16 g_qwext[(size_t)MTOT * KESb];
__device__ __nv_bfloat16 g_qkT  [(size_t)BATCH * KESb * SEQ];
__device__ __nv_bfloat16 g_Pext [(size_t)BATCH * SEQ * KEAb];
__device__ __nv_bfloat16 g_vext [(size_t)BATCH * KEAb * INTER];
__device__ __nv_bfloat16 g_pvext[(size_t)MTOT * KEOb];
__device__ __nv_bfloat16 g_Woext[(size_t)KEOb * HID];

__device__ __forceinline__ void bsplit(float v, __nv_bfloat16& h, __nv_bfloat16& l) {
    h = __float2bfloat16(v);
    l = __float2bfloat16(v - __bfloat162float(h));
}
__device__ __forceinline__ uint32_t smem_u32(const void* p) {
    uint32_t a;
    asm("{ .reg .u64 t; cvta.to.shared.u64 t, %1; cvt.u32.u64 %0, t; }" : "=r"(a) : "l"(p));
    return a;
}
#define LDMX4(r0,r1,r2,r3,addr) \
    asm volatile("ldmatrix.sync.aligned.m8n8.x4.shared.b16 {%0,%1,%2,%3}, [%4];" \
        : "=r"(r0),"=r"(r1),"=r"(r2),"=r"(r3) : "r"(addr))
#define LDMT4(r0,r1,r2,r3,addr) \
    asm volatile("ldmatrix.sync.aligned.m8n8.x4.trans.shared.b16 {%0,%1,%2,%3}, [%4];" \
        : "=r"(r0),"=r"(r1),"=r"(r2),"=r"(r3) : "r"(addr))
#define MMA16816(d, a, b0, b1) \
    asm volatile("mma.sync.aligned.m16n8k16.row.col.f32.bf16.bf16.f32 " \
        "{%0,%1,%2,%3},{%4,%5,%6,%7},{%8,%9},{%0,%1,%2,%3};" \
        : "+f"((d)[0]),"+f"((d)[1]),"+f"((d)[2]),"+f"((d)[3]) \
        : "r"((a)[0]),"r"((a)[1]),"r"((a)[2]),"r"((a)[3]),"r"(b0),"r"(b1))

__global__ void compute_scale_k(const int* __restrict__ mask)
{
    int b = blockIdx.x, t = threadIdx.x;
    int s = 0;
    for (int i = t; i < SEQ; i += 256) s += mask[(long)b*SEQ + i];
#pragma unroll
    for (int o = 16; o > 0; o >>= 1) s += __shfl_xor_sync(0xffffffffu, s, o);
    __shared__ int red[8];
    if ((t & 31) == 0) red[t >> 5] = s;
    __syncthreads();
    if (t == 0) {
        int tot = 0;
#pragma unroll
        for (int i = 0; i < 8; i++) tot += red[i];
        g_scale[b] = logf((float)tot) / (6.2383246250395075f * 11.313708498984761f);
    }
}

// hidden[r, c4*4..+3] -> Hext[r, c]=h..., [r, HID+c]=l...
__global__ void conv_H(const float* __restrict__ Hs)
{
    long idx = (long)blockIdx.x * 256 + threadIdx.x;          // MTOT*HID/4
    long r = idx / (HID/4); int c = (int)(idx % (HID/4)) * 4;
    float4 v = *(const float4*)(Hs + r * HID + c);
    __nv_bfloat16 hv[4], lv[4];
    bsplit(v.x, hv[0], lv[0]); bsplit(v.y, hv[1], lv[1]);
    bsplit(v.z, hv[2], lv[2]); bsplit(v.w, hv[3], lv[3]);
    __nv_bfloat16* p = g_Hext + r * KE1b + c;
    *(uint2*)(p)       = *(uint2*)hv;
    *(uint2*)(p + HID) = *(uint2*)lv;
}

__global__ void conv_Wi(const float* __restrict__ Wi)
{
    long idx = (long)blockIdx.x * 256 + threadIdx.x;          // HID*NCOL/4
    long r = idx / (NCOL/4); int c = (int)(idx % (NCOL/4)) * 4;
    float4 v = *(const float4*)(Wi + r * NCOL + c);
    __nv_bfloat16 hv[4], lv[4];
    bsplit(v.x, hv[0], lv[0]); bsplit(v.y, hv[1], lv[1]);
    bsplit(v.z, hv[2], lv[2]); bsplit(v.w, hv[3], lv[3]);
    *(uint2*)(g_Wiext +  r        * (long)NCOL + c) = *(uint2*)hv;
    *(uint2*)(g_Wiext + (r + HID) * (long)NCOL + c) = *(uint2*)lv;
}

__global__ void conv_Wo(const float* __restrict__ Wo)
{
    long idx = (long)blockIdx.x * 256 + threadIdx.x;          // INTER*HID/4
    long r = idx / (HID/4); int c = (int)(idx % (HID/4)) * 4;
    float4 v = *(const float4*)(Wo + r * HID + c);
    __nv_bfloat16 hv[4], lv[4];
    bsplit(v.x, hv[0], lv[0]); bsplit(v.y, hv[1], lv[1]);
    bsplit(v.z, hv[2], lv[2]); bsplit(v.w, hv[3], lv[3]);
    *(uint2*)(g_Woext +  r          * (long)HID + c) = *(uint2*)hv;
    *(uint2*)(g_Woext + (r + INTER) * (long)HID + c) = *(uint2*)lv;
}

__global__ void conv_qk(const float* __restrict__ qg, const float* __restrict__ kg)
{
    long idx = (long)blockIdx.x * 256 + threadIdx.x;          // MTOT*DK/4
    long gr = idx / (DK/4); int d = (int)(idx % (DK/4)) * 4;
    float4 v = *(const float4*)(g_x + gr * NCOL + 2*INTER + d);
    float xv[4] = {v.x, v.y, v.z, v.w};
    __nv_bfloat16 qh[4], ql[4];
#pragma unroll
    for (int i = 0; i < 4; i++) bsplit(xv[i] * qg[d+i] * kg[d+i], qh[i], ql[i]);
    __nv_bfloat16* p = g_qwext + gr * KESb + d;
    *(uint2*)(p)      = *(uint2*)qh;
    *(uint2*)(p + DK) = *(uint2*)ql;
    long b = gr >> 11, n = gr & (SEQ - 1);
    __nv_bfloat16* q = g_qkT + b * (long)KESb * SEQ + n;
#pragma unroll
    for (int i = 0; i < 4; i++) {
        __nv_bfloat16 h, l; bsplit(xv[i], h, l);
        q[(long)(d+i) * SEQ]      = h;
        q[(long)(DK+d+i) * SEQ]   = l;
    }
}

__global__ void conv_v(int dummy)
{
    long idx = (long)blockIdx.x * 256 + threadIdx.x;          // MTOT*INTER/4
    long gr = idx / (INTER/4); int j = (int)(idx % (INTER/4)) * 4;
    float4 v = *(const float4*)(g_x + gr * NCOL + INTER + j);
    __nv_bfloat16 hv[4], lv[4];
    bsplit(v.x, hv[0], lv[0]); bsplit(v.y, hv[1], lv[1]);
    bsplit(v.z, hv[2], lv[2]); bsplit(v.w, hv[3], lv[3]);
    long b = gr >> 11, n = gr & (SEQ - 1);
    __nv_bfloat16* p = g_vext + b * (long)KEAb * INTER + j;
    *(uint2*)(p +  n        * (long)INTER) = *(uint2*)hv;
    *(uint2*)(p + (n + SEQ) * (long)INTER) = *(uint2*)lv;
}

__global__ __launch_bounds__(256) void softmax_rows(int dummy)
{
    long gr = blockIdx.x;
    const float* p = g_A + gr * SEQ;
    long b = gr >> 11, m = gr & (SEQ - 1);
    __nv_bfloat16* pe = g_Pext + b * (long)SEQ * KEAb + m * (long)KEAb;

    int t = threadIdx.x;
    float v[8];
    float mx = -3.4e38f;
#pragma unroll
    for (int i = 0; i < 8; i++) { v[i] = p[t + (i << 8)]; mx = fmaxf(mx, v[i]); }
    __shared__ float smax[8], ssum[8];
#pragma unroll
    for (int o = 16; o > 0; o >>= 1) mx = fmaxf(mx, __shfl_xor_sync(0xffffffffu, mx, o));
    if ((t & 31) == 0) smax[t >> 5] = mx;
    __syncthreads();
    if (t < 32) {
        float m2 = (t < 8) ? smax[t] : -3.4e38f;
#pragma unroll
        for (int o = 4; o > 0; o >>= 1) m2 = fmaxf(m2, __shfl_xor_sync(0xffffffffu, m2, o));
        if (t == 0) smax[0] = m2;
    }
    __syncthreads();
    mx = smax[0];
    float s = 0.f;
#pragma unroll
    for (int i = 0; i < 8; i++) { v[i] = expf(v[i] - mx); s += v[i]; }
#pragma unroll
    for (int o = 16; o > 0; o >>= 1) s += __shfl_xor_sync(0xffffffffu, s, o);
    if ((t & 31) == 0) ssum[t >> 5] = s;
    __syncthreads();
    if (t < 32) {
        float m2 = (t < 8) ? ssum[t] : 0.f;
#pragma unroll
        for (int o = 4; o > 0; o >>= 1) m2 += __shfl_xor_sync(0xffffffffu, m2, o);
        if (t == 0) ssum[0] = m2;
    }
    __syncthreads();
    float inv = 1.0f / ssum[0];
#pragma unroll
    for (int i = 0; i < 8; i++) {
        int n = t + (i << 8);
        __nv_bfloat16 h, l; bsplit(v[i] * inv, h, l);
        pe[n] = h; pe[SEQ + n] = l;
    }
}

// ---------------------------------------------------------------------------
// bf16 tensor-core GEMM over [h|l] storage with 3-term chunk scheduling:
//   term0: A[0..K0) x B[0..K0)    (ah*bh)
//   term1: A[0..K0) x B[K0..2K0)  (ah*bl)
//   term2: A[K0..2K0) x B[0..K0)  (al*bh)
// Tile 128x128, 256 threads, warp grid 4x2, register-prefetch mainloop (R9).
// ---------------------------------------------------------------------------
template<int MODE>
__global__ __launch_bounds__(256) void bmma_gemm(
    const __nv_bfloat16* __restrict__ A, int lda, long sA,
    const __nv_bfloat16* __restrict__ B, int ldb, long sB,
    float* __restrict__ Cf, int ldc, long sC,
    __nv_bfloat16* __restrict__ Cb, long sCb,
    const float* __restrict__ U, long sU,
    const int* __restrict__ maskb,
    int K0)
{
    const int bz = blockIdx.z;
    A += (long)bz * sA;
    B += (long)bz * sB;
    const int* mk = (MODE == 2) ? (maskb + (long)bz * SEQ) : nullptr;

    __shared__ __align__(16) __nv_bfloat16 As[128][40];
    __shared__ __align__(16) __nv_bfloat16 Bs[32][136];

    const int tid  = threadIdx.x;
    const int lane = tid & 31;
    const int wid  = tid >> 5;
    const int warp_m = wid >> 1;
    const int warp_n = wid & 1;
    const int brow = blockIdx.y * 128;
    const int bcol = blockIdx.x * 128;

    const int aRow = tid >> 2,  aCol = (tid & 3) * 8;
    const int bRow = tid >> 4,  bCol = (tid & 15) * 8;

    const __nv_bfloat16* Abase0 = A + (long)(brow + aRow)      * lda + aCol;
    const __nv_bfloat16* Abase1 = A + (long)(brow + aRow + 64) * lda + aCol;
    const __nv_bfloat16* Bbase  = B + bcol + bCol;

    const uint32_t asBase = smem_u32(&As[0][0]);
    const uint32_t bsBase = smem_u32(&Bs[0][0]);
    const int aLmRow = warp_m * 32 + ((lane >> 3) & 1) * 8 + (lane & 7);
    const int aLmCol = (lane >> 4) * 8;
    const int bLmRow = ((lane >> 3) & 1) * 8 + (lane & 7);
    const int bLmCol = warp_n * 64 + (lane >> 4) * 8;

    float acc[2][8][4] = {};

    const int nk0 = K0 >> 5;          // chunks per term
    const int nK  = 3 * nk0;

    int ao, bo;
    {
        // chunk 0 offsets
        ao = 0; bo = 0;
    }
    int4 ra0 = *(const int4*)(Abase0 + ao);
    int4 ra1 = *(const int4*)(Abase1 + ao);
    int4 rb0 = *(const int4*)(Bbase + (long)(bo + bRow)      * ldb);
    int4 rb1 = *(const int4*)(Bbase + (long)(bo + bRow + 16) * ldb);

    for (int kc = 0; kc < nK; kc++) {
        *(int4*)&As[aRow][aCol]      = ra0;
        *(int4*)&As[aRow + 64][aCol] = ra1;
        *(int4*)&Bs[bRow][bCol]      = rb0;
        *(int4*)&Bs[bRow + 16][bCol] = rb1;
        __syncthreads();

        if (kc + 1 < nK) {
            int s = kc + 1;
            int seg = s / nk0, r = s - seg * nk0;
            ao = ((seg == 2) ? K0 : 0) + (r << 5);
            bo = ((seg == 1) ? K0 : 0) + (r << 5);
            ra0 = *(const int4*)(Abase0 + ao);
            ra1 = *(const int4*)(Abase1 + ao);
            rb0 = *(const int4*)(Bbase + (long)(bo + bRow)      * ldb);
            rb1 = *(const int4*)(Bbase + (long)(bo + bRow + 16) * ldb);
        }

#pragma unroll
        for (int kk = 0; kk < 2; kk++) {
            uint32_t a[2][4];
#pragma unroll
            for (int mf = 0; mf < 2; mf++) {
                uint32_t addr = asBase + (uint32_t)(((aLmRow + mf*16) * 40 + aLmCol + kk*16) * 2);
                LDMX4(a[mf][0], a[mf][1], a[mf][2], a[mf][3], addr);
            }
            uint32_t b[4][4];
#pragma unroll
            for (int p = 0; p < 4; p++) {
                uint32_t addr = bsBase + (uint32_t)(((bLmRow + kk*16) * 136 + bLmCol + p*16) * 2);
                LDMT4(b[p][0], b[p][1], b[p][2], b[p][3], addr);
            }
#pragma unroll
            for (int mf = 0; mf < 2; mf++)
#pragma unroll
                for (int nf = 0; nf < 8; nf++)
                    MMA16816(acc[mf][nf], a[mf], b[nf >> 1][(nf & 1) * 2], b[nf >> 1][(nf & 1) * 2 + 1]);
        }
        __syncthreads();
    }

    const int lr = lane >> 2, lc = (lane & 3) * 2;
    float scl = (MODE == 2) ? g_scale[bz] : 0.f;

#pragma unroll
    for (int mf = 0; mf < 2; mf++) {
#pragma unroll
        for (int i = 0; i < 2; i++) {
            int row = brow + warp_m * 32 + mf * 16 + i * 8 + lr;
#pragma unroll
            for (int nf = 0; nf < 8; nf++) {
                int col = bcol + warp_n * 64 + nf * 8 + lc;
                float v0 = acc[mf][nf][i * 2 + 0];
                float v1 = acc[mf][nf][i * 2 + 1];
                if (MODE == 0) {
                    float2* c = (float2*)(Cf + (long)bz * sC + (long)row * ldc + col);
                    *c = make_float2(v0, v1);
                } else if (MODE == 1) {
                    v0 = v0 / (1.0f + expf(-v0));
                    v1 = v1 / (1.0f + expf(-v1));
                    float2* c = (float2*)(Cf + (long)bz * sC + (long)row * ldc + col);
                    *c = make_float2(v0, v1);
                } else if (MODE == 2) {
                    v0 *= scl; v1 *= scl;
                    if (mk[col]     == 0) v0 = -1e30f;
                    if (mk[col + 1] == 0) v1 = -1e30f;
                    float2* c = (float2*)(Cf + (long)bz * sC + (long)row * ldc + col);
                    *c = make_float2(v0, v1);
                } else {
                    const float2 u = *(const float2*)(U + (long)bz * sU + (long)row * NCOL + col);
                    v0 *= u.x; v1 *= u.y;
                    __nv_bfloat16 h0, l0, h1, l1;
                    bsplit(v0, h0, l0); bsplit(v1, h1, l1);
                    __nv_bfloat16* c = Cb + (long)bz * sCb + (long)row * KEOb + col;
                    *(__nv_bfloat162*)(c)         = __halves2bfloat162(h0, h1);
                    *(__nv_bfloat162*)(c + INTER) = __halves2bfloat162(l0, l1);
                }
            }
        }
    }
}

extern "C" void kernel_launch(void* const* d_in, const int* in_sizes, int n_in,
                              void* d_out, int out_size)
{
    (void)in_sizes; (void)n_in; (void)out_size;
    const float* hidden = (const float*)d_in[0];
    const float* Wi     = (const float*)d_in[1];
    const float* Wo     = (const float*)d_in[2];
    const float* qg     = (const float*)d_in[3];
    const float* kg     = (const float*)d_in[4];
    const int*   mask   = (const int*)  d_in[5];
    float* out = (float*)d_out;

    float *px, *pA;
    __nv_bfloat16 *pH, *pWi, *pqw, *pqkT, *pP, *pv, *ppv, *pWo;
    cudaGetSymbolAddress((void**)&px,  g_x);
    cudaGetSymbolAddress((void**)&pA,  g_A);
    cudaGetSymbolAddress((void**)&pH,  g_Hext);
    cudaGetSymbolAddress((void**)&pWi, g_Wiext);
    cudaGetSymbolAddress((void**)&pqw, g_qwext);
    cudaGetSymbolAddress((void**)&pqkT,g_qkT);
    cudaGetSymbolAddress((void**)&pP,  g_Pext);
    cudaGetSymbolAddress((void**)&pv,  g_vext);
    cudaGetSymbolAddress((void**)&ppv, g_pvext);
    cudaGetSymbolAddress((void**)&pWo, g_Woext);

    compute_scale_k<<<BATCH, 256>>>(mask);
    conv_H <<<(MTOT*HID/4)/256, 256>>>(hidden);
    conv_Wi<<<(HID*NCOL/4)/256, 256>>>(Wi);
    conv_Wo<<<(INTER*HID/4)/256, 256>>>(Wo);

    // 1) x = silu(H @ Wi)   [8192 x 3200], K0=768
    bmma_gemm<1><<<dim3(NCOL/128, MTOT/128, 1), 256>>>(
        pH, KE1b, 0, pWi, NCOL, 0, px, NCOL, 0,
        nullptr, 0, nullptr, 0, nullptr, HID);

    conv_qk<<<(MTOT*DK/4)/256, 256>>>(qg, kg);
    conv_v <<<(MTOT*INTER/4)/256, 256>>>(0);

    // 2) scores [4 x 2048 x 2048], K0=128
    bmma_gemm<2><<<dim3(SEQ/128, SEQ/128, BATCH), 256>>>(
        pqw, KESb, (long)SEQ*KESb, pqkT, SEQ, (long)KESb*SEQ,
        pA, SEQ, (long)SEQ*SEQ,
        nullptr, 0, nullptr, 0, mask, DK);

    softmax_rows<<<MTOT, 256>>>(0);

    // 3) pv = u * (P @ v)   [4 x 2048 x 1536], K0=2048
    bmma_gemm<3><<<dim3(INTER/128, SEQ/128, BATCH), 256>>>(
        pP, KEAb, (long)SEQ*KEAb, pv, INTER, (long)KEAb*INTER,
        nullptr, 0, 0,
        ppv, (long)SEQ*KEOb, px, (long)SEQ*NCOL, nullptr, SEQ);

    // 4) out = pv @ Wo   [8192 x 768], K0=1536
    bmma_gemm<0><<<dim3(HID/128, MTOT/128, 1), 256>>>(
        ppv, KEOb, 0, pWo, HID, 0, out, HID, 0,
        nullptr, 0, nullptr, 0, nullptr, INTER);
}